// round 7
// baseline (speedup 1.0000x reference)
#include <cuda_runtime.h>

// Problem dims
#define NB 128   // batch
#define NI 256   // in_features
#define NH 128   // H
#define NO 32    // OUT

#define DROW 260    // padded d-row stride in floats (conflict-free strip reads)
#define PSTRIDE 18  // u64 stride for partial exchange (conflict-free)

// Scratch: w[b][h][o]  (fully overwritten every launch -> no init needed)
__device__ float g_w[NB * NH * NO];
// Grid-barrier counters (reset to 0 by the last departing CTA each launch)
__device__ unsigned int g_arrive = 0;
__device__ unsigned int g_depart = 0;

__device__ __forceinline__ unsigned long long pack_dup(float v) {
    unsigned long long r;
    unsigned int b = __float_as_uint(v);
    asm("mov.b64 %0, {%1, %1};" : "=l"(r) : "r"(b));
    return r;
}

__device__ __forceinline__ void fma2(unsigned long long& a,
                                     unsigned long long t,
                                     unsigned long long d) {
    asm("fma.rn.f32x2 %0, %1, %2, %3;" : "=l"(a) : "l"(t), "l"(d), "l"(a));
}

// ---------------------------------------------------------------------------
// Fused kernel: ONE CTA per h (128 CTAs, single wave -> grid barrier is safe).
//   Part 1 (per-h GEMV bundle): identical to round-6 main.
//   Grid barrier (counter + spin).
//   Part 2: CTA b=blockIdx reduces its g_w row -> final outputs. No 2nd launch.
// ---------------------------------------------------------------------------
__global__ __launch_bounds__(256, 1) void order1_fused(
    const float* __restrict__ input,      // [NB][NI]
    const float* __restrict__ sigma_psi,  // [NI][NH][NO]
    const float* __restrict__ chi,        // [NI][NH]
    const float* __restrict__ sigma_eps,  // [NH][NO]
    const float* __restrict__ eta,        // [NH][NO]
    const float* __restrict__ mu_phi,     // [NO]
    const float* __restrict__ sigma_phi,  // [NO]
    float* __restrict__ out, int out_size)
{
    extern __shared__ float smem[];
    float* Ts = smem;            // [NI][NO]   = 8192 floats
    float* dS = smem + NI * NO;  // [NB][DROW] = 33280 floats

    const int h   = blockIdx.x;
    const int tid = threadIdx.x;

    // ---- Phase 1: Ts[i][o] = sigma_psi[i,h,o]^2 (float4, coalesced) ----
    {
        const float4* sp4 = reinterpret_cast<const float4*>(sigma_psi);
        float4* Ts4 = reinterpret_cast<float4*>(Ts);
#pragma unroll
        for (int k = 0; k < 8; k++) {
            int idx4 = tid + k * 256;          // 0..2047
            int i  = idx4 >> 3;
            int o4 = idx4 & 7;
            float4 v = sp4[(i * NH + h) * 8 + o4];
            v.x *= v.x; v.y *= v.y; v.z *= v.z; v.w *= v.w;
            Ts4[idx4] = v;
        }
    }

    // ---- Phase 2: dS[b][i] = (chi[i,h] - x[b,i])^2 for ALL 128 b ----
    {
        const int iq = tid & 63;   // i-quad
        const int bb = tid >> 6;   // 0..3 (uniform within warp)
        const int i  = iq * 4;
        const float c0 = chi[(i + 0) * NH + h];
        const float c1 = chi[(i + 1) * NH + h];
        const float c2 = chi[(i + 2) * NH + h];
        const float c3 = chi[(i + 3) * NH + h];
#pragma unroll 4
        for (int k = 0; k < 32; k++) {
            const int b = bb + 4 * k;
            float4 x4 = *reinterpret_cast<const float4*>(input + b * NI + i);
            float4 d4;
            d4.x = (c0 - x4.x) * (c0 - x4.x);
            d4.y = (c1 - x4.y) * (c1 - x4.y);
            d4.z = (c2 - x4.z) * (c2 - x4.z);
            d4.w = (c3 - x4.w) * (c3 - x4.w);
            *reinterpret_cast<float4*>(dS + b * DROW + i) = d4;
        }
    }
    __syncthreads();

    // ---- Phase 3: warp = (og, half); lane carries 4 b-strips in regs ----
    const int w    = tid >> 5;
    const int lane = tid & 31;
    const int og   = w & 3;
    const int half = w >> 2;
    const int i0   = half * 128;
    const float* Tcol = Ts + og * 8;

    unsigned long long acc[4][4];   // [b-strip][o-pair]
#pragma unroll
    for (int r = 0; r < 4; r++)
#pragma unroll
        for (int p = 0; p < 4; p++) acc[r][p] = 0ull;

    const float* dR0 = dS + (lane      ) * DROW;
    const float* dR1 = dS + (lane + 32 ) * DROW;
    const float* dR2 = dS + (lane + 64 ) * DROW;
    const float* dR3 = dS + (lane + 96 ) * DROW;

#pragma unroll 2
    for (int i = i0; i < i0 + 128; i += 4) {
        float4 dv0 = *reinterpret_cast<const float4*>(dR0 + i);
        float4 dv1 = *reinterpret_cast<const float4*>(dR1 + i);
        float4 dv2 = *reinterpret_cast<const float4*>(dR2 + i);
        float4 dv3 = *reinterpret_cast<const float4*>(dR3 + i);
#pragma unroll
        for (int rr = 0; rr < 4; rr++) {
            ulonglong2 ta = *reinterpret_cast<const ulonglong2*>(Tcol + (i + rr) * NO);
            ulonglong2 tb = *reinterpret_cast<const ulonglong2*>(Tcol + (i + rr) * NO + 4);
            float f0 = (rr == 0) ? dv0.x : (rr == 1) ? dv0.y : (rr == 2) ? dv0.z : dv0.w;
            float f1 = (rr == 0) ? dv1.x : (rr == 1) ? dv1.y : (rr == 2) ? dv1.z : dv1.w;
            float f2 = (rr == 0) ? dv2.x : (rr == 1) ? dv2.y : (rr == 2) ? dv2.z : dv2.w;
            float f3 = (rr == 0) ? dv3.x : (rr == 1) ? dv3.y : (rr == 2) ? dv3.z : dv3.w;
            unsigned long long dd0 = pack_dup(f0);
            unsigned long long dd1 = pack_dup(f1);
            unsigned long long dd2 = pack_dup(f2);
            unsigned long long dd3 = pack_dup(f3);
            fma2(acc[0][0], ta.x, dd0); fma2(acc[0][1], ta.y, dd0);
            fma2(acc[0][2], tb.x, dd0); fma2(acc[0][3], tb.y, dd0);
            fma2(acc[1][0], ta.x, dd1); fma2(acc[1][1], ta.y, dd1);
            fma2(acc[1][2], tb.x, dd1); fma2(acc[1][3], tb.y, dd1);
            fma2(acc[2][0], ta.x, dd2); fma2(acc[2][1], ta.y, dd2);
            fma2(acc[2][2], tb.x, dd2); fma2(acc[2][3], tb.y, dd2);
            fma2(acc[3][0], ta.x, dd3); fma2(acc[3][1], ta.y, dd3);
            fma2(acc[3][2], tb.x, dd3); fma2(acc[3][3], tb.y, dd3);
        }
    }

    // ---- Exchange i-halves + epilogue: g_w[b][h][o] = 1/(s+eps^2) ----
    __syncthreads();   // everyone done reading dS
    unsigned long long* P = reinterpret_cast<unsigned long long*>(dS);
    if (half == 1) {
        ulonglong2* p2 =
            reinterpret_cast<ulonglong2*>(P + (og * 32 + lane) * PSTRIDE);
#pragma unroll
        for (int k = 0; k < 8; k++)
            p2[k] = make_ulonglong2(acc[k >> 1][(k & 1) * 2],
                                    acc[k >> 1][(k & 1) * 2 + 1]);
    }
    __syncthreads();

    if (half == 0) {
        float ev[8];
#pragma unroll
        for (int k = 0; k < 8; k++) {
            float e = sigma_eps[h * NO + og * 8 + k];
            ev[k] = e * e;
        }
        const ulonglong2* p2 =
            reinterpret_cast<const ulonglong2*>(P + (og * 32 + lane) * PSTRIDE);
#pragma unroll
        for (int r = 0; r < 4; r++) {
            float wv[8];
#pragma unroll
            for (int q = 0; q < 4; q += 2) {
                ulonglong2 oth = p2[r * 2 + (q >> 1)];
                unsigned long long opair[2] = {oth.x, oth.y};
#pragma unroll
                for (int j = 0; j < 2; j++) {
                    unsigned int mlo, mhi, olo, ohi;
                    asm("mov.b64 {%0, %1}, %2;" : "=r"(mlo), "=r"(mhi) : "l"(acc[r][q + j]));
                    asm("mov.b64 {%0, %1}, %2;" : "=r"(olo), "=r"(ohi) : "l"(opair[j]));
                    float s0 = __uint_as_float(mlo) + __uint_as_float(olo);
                    float s1 = __uint_as_float(mhi) + __uint_as_float(ohi);
                    int oo = (q + j) * 2;
                    wv[oo]     = __fdividef(1.0f, s0 + ev[oo]);
                    wv[oo + 1] = __fdividef(1.0f, s1 + ev[oo + 1]);
                }
            }
            const int b = r * 32 + lane;
            float* gp = g_w + (b * NH + h) * NO + og * 8;   // [b][h][o]
            *reinterpret_cast<float4*>(gp)     = make_float4(wv[0], wv[1], wv[2], wv[3]);
            *reinterpret_cast<float4*>(gp + 4) = make_float4(wv[4], wv[5], wv[6], wv[7]);
        }
    }

    // =========== Grid barrier (single wave: 128 CTAs <= 148 SMs) ===========
    __threadfence();          // publish g_w stores (all threads)
    __syncthreads();
    if (tid == 0) {
        atomicAdd(&g_arrive, 1u);
        while (atomicAdd(&g_arrive, 0u) < (unsigned)NH) __nanosleep(128);
    }
    __syncthreads();

    // =========== Part 2: finish for batch b = blockIdx.x ===========
    {
        const int b = blockIdx.x;
        float4* sA = reinterpret_cast<float4*>(smem);        // [8 warps][8 segs]
        float4* sB = sA + 64;

        const float4* row4 = reinterpret_cast<const float4*>(g_w + b * NH * NO);
        const float4* eta4 = reinterpret_cast<const float4*>(eta);

        float4 sw  = make_float4(0.f, 0.f, 0.f, 0.f);
        float4 swe = make_float4(0.f, 0.f, 0.f, 0.f);
#pragma unroll
        for (int k = 0; k < 4; k++) {
            int idx = tid + k * 256;            // seg = idx&7 constant over k
            float4 w4 = __ldcg(row4 + idx);     // L1-bypass: cross-SM coherent
            float4 e4 = eta4[idx];
            sw.x += w4.x; sw.y += w4.y; sw.z += w4.z; sw.w += w4.w;
            swe.x += w4.x * e4.x; swe.y += w4.y * e4.y;
            swe.z += w4.z * e4.z; swe.w += w4.w * e4.w;
        }
        // reduce h-bits in lane bits 3,4 (seg = lane&7 preserved)
#pragma unroll
        for (int m = 8; m <= 16; m <<= 1) {
            sw.x += __shfl_xor_sync(0xffffffffu, sw.x, m);
            sw.y += __shfl_xor_sync(0xffffffffu, sw.y, m);
            sw.z += __shfl_xor_sync(0xffffffffu, sw.z, m);
            sw.w += __shfl_xor_sync(0xffffffffu, sw.w, m);
            swe.x += __shfl_xor_sync(0xffffffffu, swe.x, m);
            swe.y += __shfl_xor_sync(0xffffffffu, swe.y, m);
            swe.z += __shfl_xor_sync(0xffffffffu, swe.z, m);
            swe.w += __shfl_xor_sync(0xffffffffu, swe.w, m);
        }
        if (lane < 8) {
            sA[w * 8 + lane] = sw;
            sB[w * 8 + lane] = swe;
        }
        __syncthreads();

        if (tid < 8) {
            float4 a = sA[tid], bb = sB[tid];
#pragma unroll
            for (int k = 1; k < 8; k++) {
                float4 a2 = sA[k * 8 + tid], b2 = sB[k * 8 + tid];
                a.x += a2.x; a.y += a2.y; a.z += a2.z; a.w += a2.w;
                bb.x += b2.x; bb.y += b2.y; bb.z += b2.z; bb.w += b2.w;
            }
            const int o = tid * 4;
            float4 mp = *reinterpret_cast<const float4*>(mu_phi + o);
            float4 sp = *reinterpret_cast<const float4*>(sigma_phi + o);
            float swa[4]  = {a.x, a.y, a.z, a.w};
            float swea[4] = {bb.x, bb.y, bb.z, bb.w};
            float mpa[4]  = {mp.x, mp.y, mp.z, mp.w};
            float spa[4]  = {sp.x, sp.y, sp.z, sp.w};
            float pm[4], ps[4];
#pragma unroll
            for (int c = 0; c < 4; c++) {
                float sp2 = spa[c] * spa[c];
                float inv = __fdividef(1.0f, fmaf(sp2, swa[c], 1.0f));
                pm[c] = (mpa[c] + sp2 * swea[c]) * inv;
                ps[c] = sp2 * inv;
            }
            *reinterpret_cast<float4*>(out + b * NO + o) =
                make_float4(pm[0], pm[1], pm[2], pm[3]);
            if (out_size >= 2 * NB * NO)
                *reinterpret_cast<float4*>(out + NB * NO + b * NO + o) =
                    make_float4(ps[0], ps[1], ps[2], ps[3]);
        }
    }

    // =========== Reset counters for the next graph replay ===========
    __syncthreads();
    if (tid == 0) {
        unsigned int v = atomicAdd(&g_depart, 1u);
        if (v == (unsigned)NH - 1u) {
            g_arrive = 0u;
            g_depart = 0u;
            __threadfence();
        }
    }
}

extern "C" void kernel_launch(void* const* d_in, const int* in_sizes, int n_in,
                              void* d_out, int out_size) {
    const float* input     = (const float*)d_in[0];
    const float* sigma_psi = (const float*)d_in[1];
    const float* chi       = (const float*)d_in[2];
    const float* sigma_eps = (const float*)d_in[3];
    const float* eta       = (const float*)d_in[4];
    const float* mu_phi    = (const float*)d_in[5];
    const float* sigma_phi = (const float*)d_in[6];

    const int smemA = (NI * NO + NB * DROW) * (int)sizeof(float);  // 165888 B
    cudaFuncSetAttribute(order1_fused,
                         cudaFuncAttributeMaxDynamicSharedMemorySize, smemA);

    order1_fused<<<NH, 256, smemA>>>(input, sigma_psi, chi, sigma_eps,
                                     eta, mu_phi, sigma_phi,
                                     (float*)d_out, out_size);
}

// round 8
// speedup vs baseline: 1.1175x; 1.1175x over previous
#include <cuda_runtime.h>

// Problem dims
#define NB 128   // batch
#define NI 256   // in_features
#define NH 128   // H
#define NO 32    // OUT

#define DROW 260    // padded d-row stride in floats (conflict-free strip reads)
#define PSTRIDE 18  // u64 stride per exchange slot
#define PREGION 2304 // u64 per exchange region (128 slots * 18)

// Scratch: w[b][h][o]  (fully overwritten every launch -> no init needed)
__device__ float g_w[NB * NH * NO];

__device__ __forceinline__ unsigned long long pack_dup(float v) {
    unsigned long long r;
    unsigned int b = __float_as_uint(v);
    asm("mov.b64 %0, {%1, %1};" : "=l"(r) : "r"(b));
    return r;
}

__device__ __forceinline__ void fma2(unsigned long long& a,
                                     unsigned long long t,
                                     unsigned long long d) {
    asm("fma.rn.f32x2 %0, %1, %2, %3;" : "=l"(a) : "l"(t), "l"(d), "l"(a));
}

__device__ __forceinline__ void u64_add_to(float& a, float& b,
                                           unsigned long long v) {
    unsigned int lo, hi;
    asm("mov.b64 {%0, %1}, %2;" : "=r"(lo), "=r"(hi) : "l"(v));
    a += __uint_as_float(lo);
    b += __uint_as_float(hi);
}

// ---------------------------------------------------------------------------
// Kernel A: ONE CTA per h, 512 threads (16 warps = 4 o-groups x 4 i-quarters).
//   4 warps/SMSP -> 2x latency hiding vs round 6. Lane carries 4 b-strips in
//   registers so each T-broadcast feeds 128 b x 8 o MACs.
// ---------------------------------------------------------------------------
__global__ __launch_bounds__(512, 1) void order1_main(
    const float* __restrict__ input,      // [NB][NI]
    const float* __restrict__ sigma_psi,  // [NI][NH][NO]
    const float* __restrict__ chi,        // [NI][NH]
    const float* __restrict__ sigma_eps)  // [NH][NO]
{
    extern __shared__ float smem[];
    float* Ts = smem;            // [NI][NO]   = 8192 floats
    float* dS = smem + NI * NO;  // [NB][DROW] = 33280 floats

    const int h   = blockIdx.x;
    const int tid = threadIdx.x;

    // ---- Phase 1: Ts[i][o] = sigma_psi[i,h,o]^2 (float4, coalesced) ----
    {
        const float4* sp4 = reinterpret_cast<const float4*>(sigma_psi);
        float4* Ts4 = reinterpret_cast<float4*>(Ts);
#pragma unroll
        for (int k = 0; k < 4; k++) {
            int idx4 = tid + k * 512;          // 0..2047
            int i  = idx4 >> 3;
            int o4 = idx4 & 7;
            float4 v = sp4[(i * NH + h) * 8 + o4];
            v.x *= v.x; v.y *= v.y; v.z *= v.z; v.w *= v.w;
            Ts4[idx4] = v;
        }
    }

    // ---- Phase 2: dS[b][i] = (chi[i,h] - x[b,i])^2 for ALL 128 b ----
    {
        const int iq = tid & 63;   // i-quad
        const int bb = tid >> 6;   // 0..7 (uniform within warp)
        const int i  = iq * 4;
        const float c0 = chi[(i + 0) * NH + h];
        const float c1 = chi[(i + 1) * NH + h];
        const float c2 = chi[(i + 2) * NH + h];
        const float c3 = chi[(i + 3) * NH + h];
#pragma unroll 4
        for (int k = 0; k < 16; k++) {
            const int b = bb + 8 * k;
            float4 x4 = *reinterpret_cast<const float4*>(input + b * NI + i);
            float4 d4;
            d4.x = (c0 - x4.x) * (c0 - x4.x);
            d4.y = (c1 - x4.y) * (c1 - x4.y);
            d4.z = (c2 - x4.z) * (c2 - x4.z);
            d4.w = (c3 - x4.w) * (c3 - x4.w);
            *reinterpret_cast<float4*>(dS + b * DROW + i) = d4;
        }
    }
    __syncthreads();

    // ---- Phase 3: warp = (og, quarter). 8 o's, 64 i's per warp. ----
    const int w    = tid >> 5;
    const int lane = tid & 31;
    const int og   = w & 3;
    const int q    = w >> 2;       // i-quarter 0..3
    const int i0   = q * 64;
    const float* Tcol = Ts + og * 8;

    unsigned long long acc[4][4];   // [b-strip][o-pair]
#pragma unroll
    for (int r = 0; r < 4; r++)
#pragma unroll
        for (int p = 0; p < 4; p++) acc[r][p] = 0ull;

    const float* dR0 = dS + (lane      ) * DROW;
    const float* dR1 = dS + (lane + 32 ) * DROW;
    const float* dR2 = dS + (lane + 64 ) * DROW;
    const float* dR3 = dS + (lane + 96 ) * DROW;

#pragma unroll 2
    for (int i = i0; i < i0 + 64; i += 4) {
        float4 dv0 = *reinterpret_cast<const float4*>(dR0 + i);
        float4 dv1 = *reinterpret_cast<const float4*>(dR1 + i);
        float4 dv2 = *reinterpret_cast<const float4*>(dR2 + i);
        float4 dv3 = *reinterpret_cast<const float4*>(dR3 + i);
#pragma unroll
        for (int rr = 0; rr < 4; rr++) {
            ulonglong2 ta = *reinterpret_cast<const ulonglong2*>(Tcol + (i + rr) * NO);
            ulonglong2 tb = *reinterpret_cast<const ulonglong2*>(Tcol + (i + rr) * NO + 4);
            float f0 = (rr == 0) ? dv0.x : (rr == 1) ? dv0.y : (rr == 2) ? dv0.z : dv0.w;
            float f1 = (rr == 0) ? dv1.x : (rr == 1) ? dv1.y : (rr == 2) ? dv1.z : dv1.w;
            float f2 = (rr == 0) ? dv2.x : (rr == 1) ? dv2.y : (rr == 2) ? dv2.z : dv2.w;
            float f3 = (rr == 0) ? dv3.x : (rr == 1) ? dv3.y : (rr == 2) ? dv3.z : dv3.w;
            unsigned long long dd0 = pack_dup(f0);
            unsigned long long dd1 = pack_dup(f1);
            unsigned long long dd2 = pack_dup(f2);
            unsigned long long dd3 = pack_dup(f3);
            fma2(acc[0][0], ta.x, dd0); fma2(acc[0][1], ta.y, dd0);
            fma2(acc[0][2], tb.x, dd0); fma2(acc[0][3], tb.y, dd0);
            fma2(acc[1][0], ta.x, dd1); fma2(acc[1][1], ta.y, dd1);
            fma2(acc[1][2], tb.x, dd1); fma2(acc[1][3], tb.y, dd1);
            fma2(acc[2][0], ta.x, dd2); fma2(acc[2][1], ta.y, dd2);
            fma2(acc[2][2], tb.x, dd2); fma2(acc[2][3], tb.y, dd2);
            fma2(acc[3][0], ta.x, dd3); fma2(acc[3][1], ta.y, dd3);
            fma2(acc[3][2], tb.x, dd3); fma2(acc[3][3], tb.y, dd3);
        }
    }

    // ---- Exchange: quarters 1-3 publish partials; quarter 0 combines ----
    __syncthreads();   // everyone done reading dS
    unsigned long long* P = reinterpret_cast<unsigned long long*>(dS);
    if (q != 0) {
        ulonglong2* p2 = reinterpret_cast<ulonglong2*>(
            P + (q - 1) * PREGION + (og * 32 + lane) * PSTRIDE);
#pragma unroll
        for (int k = 0; k < 8; k++)
            p2[k] = make_ulonglong2(acc[k >> 1][(k & 1) * 2],
                                    acc[k >> 1][(k & 1) * 2 + 1]);
    }
    __syncthreads();

    if (q == 0) {
        float ev[8];
#pragma unroll
        for (int k = 0; k < 8; k++) {
            float e = sigma_eps[h * NO + og * 8 + k];
            ev[k] = e * e;
        }
#pragma unroll
        for (int r = 0; r < 4; r++) {
            float s[8];
#pragma unroll
            for (int p = 0; p < 4; p++) {
                unsigned int lo, hi;
                asm("mov.b64 {%0, %1}, %2;" : "=r"(lo), "=r"(hi) : "l"(acc[r][p]));
                s[2 * p]     = __uint_as_float(lo);
                s[2 * p + 1] = __uint_as_float(hi);
            }
#pragma unroll
            for (int reg = 0; reg < 3; reg++) {
                const ulonglong2* p2 = reinterpret_cast<const ulonglong2*>(
                    P + reg * PREGION + (og * 32 + lane) * PSTRIDE) + r * 2;
                ulonglong2 a0 = p2[0];   // o-pairs 0,1
                ulonglong2 a1 = p2[1];   // o-pairs 2,3
                u64_add_to(s[0], s[1], a0.x);
                u64_add_to(s[2], s[3], a0.y);
                u64_add_to(s[4], s[5], a1.x);
                u64_add_to(s[6], s[7], a1.y);
            }
            float wv[8];
#pragma unroll
            for (int k = 0; k < 8; k++)
                wv[k] = __fdividef(1.0f, s[k] + ev[k]);
            const int b = r * 32 + lane;
            float* gp = g_w + (b * NH + h) * NO + og * 8;   // [b][h][o]
            *reinterpret_cast<float4*>(gp)     = make_float4(wv[0], wv[1], wv[2], wv[3]);
            *reinterpret_cast<float4*>(gp + 4) = make_float4(wv[4], wv[5], wv[6], wv[7]);
        }
    }
}

// ---------------------------------------------------------------------------
// Kernel B: CTA per b, 512 threads. One coalesced float4 sweep of the 16KB
// g_w row + eta, butterfly h-reduction, tiny smem combine.
// ---------------------------------------------------------------------------
__global__ __launch_bounds__(512) void order1_finish(
    const float* __restrict__ eta,        // [NH][NO]
    const float* __restrict__ mu_phi,     // [NO]
    const float* __restrict__ sigma_phi,  // [NO]
    float* __restrict__ out, int out_size)
{
    __shared__ float4 sA[16 * 8];
    __shared__ float4 sB[16 * 8];

    const int b = blockIdx.x;
    const int t = threadIdx.x;
    const int wid = t >> 5;
    const int l = t & 31;

    const float4* row4 = reinterpret_cast<const float4*>(g_w + b * NH * NO);
    const float4* eta4 = reinterpret_cast<const float4*>(eta);

    float4 sw  = make_float4(0.f, 0.f, 0.f, 0.f);
    float4 swe = make_float4(0.f, 0.f, 0.f, 0.f);
#pragma unroll
    for (int rep = 0; rep < 2; rep++) {
        int idx = t + rep * 512;   // seg = idx&7 constant over rep
        float4 w4 = row4[idx];
        float4 e4 = eta4[idx];
        sw.x += w4.x; sw.y += w4.y; sw.z += w4.z; sw.w += w4.w;
        swe.x += w4.x * e4.x; swe.y += w4.y * e4.y;
        swe.z += w4.z * e4.z; swe.w += w4.w * e4.w;
    }

    // reduce h-bits in lane bits 3,4 (seg = lane&7 preserved)
#pragma unroll
    for (int m = 8; m <= 16; m <<= 1) {
        sw.x += __shfl_xor_sync(0xffffffffu, sw.x, m);
        sw.y += __shfl_xor_sync(0xffffffffu, sw.y, m);
        sw.z += __shfl_xor_sync(0xffffffffu, sw.z, m);
        sw.w += __shfl_xor_sync(0xffffffffu, sw.w, m);
        swe.x += __shfl_xor_sync(0xffffffffu, swe.x, m);
        swe.y += __shfl_xor_sync(0xffffffffu, swe.y, m);
        swe.z += __shfl_xor_sync(0xffffffffu, swe.z, m);
        swe.w += __shfl_xor_sync(0xffffffffu, swe.w, m);
    }
    if (l < 8) {
        sA[wid * 8 + l] = sw;
        sB[wid * 8 + l] = swe;
    }
    __syncthreads();

    if (t < 8) {
        float4 a = sA[t], bb = sB[t];
#pragma unroll
        for (int k = 1; k < 16; k++) {
            float4 a2 = sA[k * 8 + t], b2 = sB[k * 8 + t];
            a.x += a2.x; a.y += a2.y; a.z += a2.z; a.w += a2.w;
            bb.x += b2.x; bb.y += b2.y; bb.z += b2.z; bb.w += b2.w;
        }
        const int o = t * 4;
        float4 mp = *reinterpret_cast<const float4*>(mu_phi + o);
        float4 sp = *reinterpret_cast<const float4*>(sigma_phi + o);
        float swa[4]  = {a.x, a.y, a.z, a.w};
        float swea[4] = {bb.x, bb.y, bb.z, bb.w};
        float mpa[4]  = {mp.x, mp.y, mp.z, mp.w};
        float spa[4]  = {sp.x, sp.y, sp.z, sp.w};
        float pm[4], ps[4];
#pragma unroll
        for (int c = 0; c < 4; c++) {
            float sp2 = spa[c] * spa[c];
            float inv = __fdividef(1.0f, fmaf(sp2, swa[c], 1.0f));
            pm[c] = (mpa[c] + sp2 * swea[c]) * inv;
            ps[c] = sp2 * inv;
        }
        *reinterpret_cast<float4*>(out + b * NO + o) =
            make_float4(pm[0], pm[1], pm[2], pm[3]);
        if (out_size >= 2 * NB * NO)
            *reinterpret_cast<float4*>(out + NB * NO + b * NO + o) =
                make_float4(ps[0], ps[1], ps[2], ps[3]);
    }
}

extern "C" void kernel_launch(void* const* d_in, const int* in_sizes, int n_in,
                              void* d_out, int out_size) {
    const float* input     = (const float*)d_in[0];
    const float* sigma_psi = (const float*)d_in[1];
    const float* chi       = (const float*)d_in[2];
    const float* sigma_eps = (const float*)d_in[3];
    const float* eta       = (const float*)d_in[4];
    const float* mu_phi    = (const float*)d_in[5];
    const float* sigma_phi = (const float*)d_in[6];

    const int smemA = (NI * NO + NB * DROW) * (int)sizeof(float);  // 165888 B
    cudaFuncSetAttribute(order1_main,
                         cudaFuncAttributeMaxDynamicSharedMemorySize, smemA);

    order1_main<<<NH, 512, smemA>>>(input, sigma_psi, chi, sigma_eps);
    order1_finish<<<NB, 512>>>(eta, mu_phi, sigma_phi, (float*)d_out, out_size);
}